// round 16
// baseline (speedup 1.0000x reference)
#include <cuda_runtime.h>
#include <cuda_fp16.h>
#include <cstdint>
#include <cstddef>

#define ENS     7
#define S_DIM   30
#define A_DIM   8
#define IN_DIM  38
#define HID     200
#define OUT_DIM 31
#define NHID    3
#define TSAMP   128
#define NTH     512

// ---- B chunk image: 224 rows x 40 halfs (row stride 20 words) ----
#define BWH     40
#define BIMG_W  4480                      // words per chunk image (224*20)
#define BIMG_B  (BIMG_W * 4)              // 17920 bytes
#define NCHUNKS 30                        // 2 (L0) + 3*7 (hidden) + 7 (head)

// ---- SMEM layout (bytes), per CTA = 126976 -> 1 CTA/SM (512 thr) ----
#define AW      216
#define SM_A    0
#define SM_B0   (TSAMP * AW * 2)          // 55296
#define SM_TOTAL (SM_B0 + 4 * BIMG_B)     // 126976

// ---- pre-packed weight images (global scratch; L2-resident, 3.76 MB) ----
__device__ __align__(16) uint32_t g_wimg[ENS * NCHUNKS * BIMG_W];

__device__ __forceinline__ const uint32_t* chunk_src(int e, int g) {
    return g_wimg + (size_t)(e * NCHUNKS + g) * BIMG_W;
}

__device__ __forceinline__ void mma16816(float* d, const uint32_t* a, const uint32_t* b) {
    asm volatile(
        "mma.sync.aligned.m16n8k16.row.col.f32.f16.f16.f32 "
        "{%0,%1,%2,%3}, {%4,%5,%6,%7}, {%8,%9}, {%0,%1,%2,%3};"
        : "+f"(d[0]), "+f"(d[1]), "+f"(d[2]), "+f"(d[3])
        : "r"(a[0]), "r"(a[1]), "r"(a[2]), "r"(a[3]),
          "r"(b[0]), "r"(b[1]));
}
__device__ __forceinline__ void ldsm4(uint32_t* r, uint32_t addr) {
    asm volatile("ldmatrix.sync.aligned.m8n8.x4.shared.b16 {%0,%1,%2,%3}, [%4];"
        : "=r"(r[0]), "=r"(r[1]), "=r"(r[2]), "=r"(r[3]) : "r"(addr));
}
__device__ __forceinline__ void ldsm2(uint32_t* r, uint32_t addr) {
    asm volatile("ldmatrix.sync.aligned.m8n8.x2.shared.b16 {%0,%1}, [%2];"
        : "=r"(r[0]), "=r"(r[1]) : "r"(addr));
}
__device__ __forceinline__ void cp16(uint32_t smem_dst, const void* gptr) {
    asm volatile("cp.async.cg.shared.global [%0], [%1], 16;\n"
        :: "r"(smem_dst), "l"(gptr));
}
#define CP_COMMIT() asm volatile("cp.async.commit_group;\n" ::: "memory")
#define CP_WAIT0()  asm volatile("cp.async.wait_group 0;\n" ::: "memory")
#define CP_WAIT1()  asm volatile("cp.async.wait_group 1;\n" ::: "memory")
#define CP_WAIT2()  asm volatile("cp.async.wait_group 2;\n" ::: "memory")

__device__ __forceinline__ uint32_t pack2h(float x, float y) {
    __half2 h = __floats2half2_rn(x, y);
    return *reinterpret_cast<uint32_t*>(&h);
}
__device__ __forceinline__ float swishf(float x) {
    return __fdividef(x, 1.0f + __expf(-x));
}
__device__ __forceinline__ float softplusf(float z) {
    return fmaxf(z, 0.0f) + log1pf(__expf(-fabsf(z)));
}
__device__ __forceinline__ float sig_transform(float x, float mx, float mn) {
    float t = (mx - softplusf(mx - 2.0f * x)) * 0.5f;
    t = (mn + softplusf(2.0f * t - mn)) * 0.5f;
    return __expf(t);
}

// ================= prep: pack all weights into chunk images (once) =================
__global__ void prep_weights(const float* __restrict__ W1, const float* __restrict__ Wh,
                             const float* __restrict__ Wmu, const float* __restrict__ Wsig) {
    const int g = blockIdx.x, e = blockIdx.y, tid = threadIdx.x;
    uint32_t* dst = g_wimg + (size_t)(e * NCHUNKS + g) * BIMG_W;
    const float* W = nullptr; const float* W2 = nullptr;
    int krows = HID, c;
    bool head = false;
    if (g < 2)       { c = g;      W = W1 + (size_t)e * IN_DIM * HID; krows = IN_DIM; }
    else if (g < 23) { int t = g - 2; int l = t / 7; c = t % 7;
                       W = Wh + ((size_t)l * ENS + e) * HID * HID; }
    else             { head = true; c = g - 23;
                       W  = Wmu  + (size_t)e * HID * OUT_DIM;
                       W2 = Wsig + (size_t)e * HID * OUT_DIM; }
    for (int w = tid; w < BIMG_W; w += 256) {
        int n = w / 20, slot = w % 20;
        float w0 = 0.f, w1 = 0.f;
        if (slot < 16) {
            int j = c * 32 + 2 * slot;
            if (!head) {
                if (n < HID) {
                    if (j < krows)     w0 = __ldg(&W[(size_t)j * HID + n]);
                    if (j + 1 < krows) w1 = __ldg(&W[(size_t)(j + 1) * HID + n]);
                }
            } else {
                if (n < OUT_DIM) {
                    if (j < HID)     w0 = __ldg(&W[(size_t)j * OUT_DIM + n]);
                    if (j + 1 < HID) w1 = __ldg(&W[(size_t)(j + 1) * OUT_DIM + n]);
                } else if (n >= 32 && n < 32 + OUT_DIM) {
                    int nn = n - 32;
                    if (j < HID)     w0 = __ldg(&W2[(size_t)j * OUT_DIM + nn]);
                    if (j + 1 < HID) w1 = __ldg(&W2[(size_t)(j + 1) * OUT_DIM + nn]);
                }
            }
        }
        dst[w] = pack2h(w0, w1);
    }
}

// ---- stage one chunk image into a SMEM B buffer: 1120 x 16B cp.async (512 thr) ----
__device__ __forceinline__ void stage_async(uint32_t dst, const uint32_t* src, int tid) {
#pragma unroll
    for (int k = 0; k < 2; ++k) {
        int line = k * NTH + tid;
        cp16(dst + line * 16, src + line * 4);
    }
    if (tid < 96) {
        int line = 1024 + tid;
        cp16(dst + line * 16, src + line * 4);
    }
}

__global__ __launch_bounds__(NTH, 1)
void ensemble_env_prob_hmma7(
    const float* __restrict__ s, const float* __restrict__ a,
    const float* __restrict__ b1, const float* __restrict__ bh,
    const float* __restrict__ bmu, const float* __restrict__ bsig,
    const float* __restrict__ max_lv_s, const float* __restrict__ min_lv_s,
    const float* __restrict__ max_lv_r, const float* __restrict__ min_lv_r,
    float* __restrict__ out, int N)
{
    extern __shared__ char smc[];
    const uint32_t smb = (uint32_t)__cvta_generic_to_shared(smc);
    const int tid  = threadIdx.x;
    const int wid  = tid >> 5;
    const int lane = tid & 31;
    const int wm   = wid >> 2;         // 4 m-groups x 32 rows
    const int wn   = wid & 3;          // 4 n-groups x 56 cols (head: 16 cols)
    const int e    = blockIdx.y;
    const int n0   = blockIdx.x * TSAMP;

    const uint32_t bufB[4] = { smb + SM_B0,              smb + SM_B0 + BIMG_B,
                               smb + SM_B0 + 2 * BIMG_B, smb + SM_B0 + 3 * BIMG_B };

    // ldmatrix per-lane address components
    const int aRow0  = wm * 32 + (lane & 15);
    const int aColL  = (lane >> 4) * 8;
    const uint32_t aBase = smb + SM_A + aRow0 * (AW * 2);
    const int bRowL  = (lane & 7) + ((lane >> 4) << 3);
    const int bKoffL = ((lane >> 3) & 1) * 8;
    const uint32_t bLane = bRowL * (BWH * 2) + bKoffL * 2;

    // kick off the weight pipeline immediately (chunks 0..2)
    stage_async(bufB[0], chunk_src(e, 0), tid); CP_COMMIT();
    stage_async(bufB[1], chunk_src(e, 1), tid); CP_COMMIT();
    stage_async(bufB[2], chunk_src(e, 2), tid); CP_COMMIT();

    // ---- zero A (covers all k padding)
    for (int i = tid; i < (TSAMP * AW) / 2; i += NTH)
        ((uint32_t*)smc)[i] = 0u;
    __syncthreads();

    // ---- stage x = concat(s, a), fp16 into A
#pragma unroll
    for (int it = 0; it < 16; ++it) {
        int idx = it * NTH + tid;          // 8192 = 128 rows x 64 slots
        int m = idx >> 6, k = idx & 63;
        if (k < IN_DIM) {
            int n = n0 + m;
            float v = (k < S_DIM)
                    ? __ldg(&s[((size_t)n * ENS + e) * S_DIM + k])
                    : __ldg(&a[((size_t)n * ENS + e) * A_DIM + (k - S_DIM)]);
            *(uint16_t*)(smc + SM_A + m * (AW * 2) + k * 2) =
                __half_as_ushort(__float2half_rn(v));
        }
    }

    float acc[2][7][4];                    // [mf][nt][q]
    int g = 0;                             // global chunk counter

    // ================= layers 1..4 (swish epilogue back into A) =================
#pragma unroll 1
    for (int l = 0; l < 1 + NHID; ++l) {
        const float* bi = (l == 0) ? (b1 + (size_t)e * HID)
                                   : (bh + ((size_t)(l - 1) * ENS + e) * HID);
        const int nks = (l == 0) ? 3 : 13;
        const int nch = (nks + 1) >> 1;

#pragma unroll
        for (int mf = 0; mf < 2; ++mf)
#pragma unroll
            for (int nt = 0; nt < 7; ++nt)
#pragma unroll
                for (int q = 0; q < 4; ++q) acc[mf][nt][q] = 0.f;

#pragma unroll 1
        for (int c = 0; c < nch; ++c) {
            {
                const int rem = NCHUNKS - 1 - g;
                if (rem >= 2) { CP_WAIT2(); } else if (rem == 1) { CP_WAIT1(); } else { CP_WAIT0(); }
            }
            __syncthreads();                       // chunk g landed; buf (g+3)%4 free
            if (g + 3 < NCHUNKS) {
                stage_async(bufB[(g + 3) & 3], chunk_src(e, g + 3), tid);
                CP_COMMIT();
            }
            const uint32_t bB = bufB[g & 3] + bLane + (wn * 56) * (BWH * 2);
            const int nk = (nks - 2 * c > 2) ? 2 : (nks - 2 * c);
#pragma unroll
            for (int ks = 0; ks < 2; ++ks) {
                if (ks >= nk) break;
                const int kA = c * 32 + ks * 16 + aColL;
                uint32_t ah[2][4];
                ldsm4(ah[0], aBase + kA * 2);
                ldsm4(ah[1], aBase + 16 * (AW * 2) + kA * 2);
                const uint32_t bk = bB + (ks * 16) * 2;
#pragma unroll
                for (int ntp = 0; ntp < 3; ++ntp) {
                    uint32_t b4[4];
                    ldsm4(b4, bk + (ntp * 16) * (BWH * 2));
#pragma unroll
                    for (int mf = 0; mf < 2; ++mf) {
                        mma16816(acc[mf][2 * ntp],     ah[mf], b4);
                        mma16816(acc[mf][2 * ntp + 1], ah[mf], b4 + 2);
                    }
                }
                {
                    uint32_t b2[2];
                    ldsm2(b2, bk + 48 * (BWH * 2));
#pragma unroll
                    for (int mf = 0; mf < 2; ++mf)
                        mma16816(acc[mf][6], ah[mf], b2);
                }
            }
            ++g;
        }
        __syncthreads();                           // all A reads done before overwrite

        // ---- epilogue: +bias, swish, fp16, back into A (cols < 200)
        const int rr = wm * 32 + (lane >> 2);
#pragma unroll
        for (int nt = 0; nt < 7; ++nt) {
            int cc = wn * 56 + nt * 8 + (lane & 3) * 2;
            if (cc < HID) {
                float b0  = __ldg(&bi[cc]);
                float b1v = __ldg(&bi[cc + 1]);
#pragma unroll
                for (int mf = 0; mf < 2; ++mf) {
#pragma unroll
                    for (int rp = 0; rp < 2; ++rp) {
                        int row = rr + mf * 16 + rp * 8;
                        float h0 = swishf(acc[mf][nt][rp * 2]     + b0);
                        float h1 = swishf(acc[mf][nt][rp * 2 + 1] + b1v);
                        *(uint32_t*)(smc + SM_A + row * (AW * 2) + cc * 2) =
                            pack2h(h0, h1);
                    }
                }
            }
        }
    }

    // ================= head: packed [mu | sig], N = 64, warp covers 16 cols ========
#pragma unroll
    for (int mf = 0; mf < 2; ++mf)
#pragma unroll
        for (int nt = 0; nt < 2; ++nt)
#pragma unroll
            for (int q = 0; q < 4; ++q) acc[mf][nt][q] = 0.f;

#pragma unroll 1
    for (int c = 0; c < 7; ++c) {
        {
            const int rem = NCHUNKS - 1 - g;
            if (rem >= 2) { CP_WAIT2(); } else if (rem == 1) { CP_WAIT1(); } else { CP_WAIT0(); }
        }
        __syncthreads();
        if (g + 3 < NCHUNKS) {
            stage_async(bufB[(g + 3) & 3], chunk_src(e, g + 3), tid);
            CP_COMMIT();
        }
        const uint32_t bB = bufB[g & 3] + bLane + (wn * 16) * (BWH * 2);
        const int nk = (13 - 2 * c > 2) ? 2 : (13 - 2 * c);
#pragma unroll
        for (int ks = 0; ks < 2; ++ks) {
            if (ks >= nk) break;
            const int kA = c * 32 + ks * 16 + aColL;
            uint32_t ah[2][4];
            ldsm4(ah[0], aBase + kA * 2);
            ldsm4(ah[1], aBase + 16 * (AW * 2) + kA * 2);
            uint32_t b4[4];
            ldsm4(b4, bB + (ks * 16) * 2);
#pragma unroll
            for (int mf = 0; mf < 2; ++mf) {
                mma16816(acc[mf][0], ah[mf], b4);
                mma16816(acc[mf][1], ah[mf], b4 + 2);
            }
        }
        ++g;
    }

    // ================= head epilogue: direct global stores =================
    {
        const size_t NT_  = (size_t)N * ENS;
        const size_t NT30 = NT_ * 30, NT60 = NT_ * 60, NT61 = NT_ * 61;
        const bool  is_sig = (wn >= 2);
        const float* bo = (is_sig ? bsig : bmu) + (size_t)e * OUT_DIM;
        const int rr = wm * 32 + (lane >> 2);
#pragma unroll
        for (int mf = 0; mf < 2; ++mf) {
#pragma unroll
            for (int rp = 0; rp < 2; ++rp) {
                int row = rr + mf * 16 + rp * 8;
                size_t base = ((size_t)(n0 + row) * ENS + e);
#pragma unroll
                for (int nt = 0; nt < 2; ++nt) {
#pragma unroll
                    for (int i = 0; i < 2; ++i) {
                        int colg = wn * 16 + nt * 8 + (lane & 3) * 2 + i;  // 0..63
                        int col  = is_sig ? (colg - 32) : colg;            // 0..31
                        float v = acc[mf][nt][rp * 2 + i];
                        if (!is_sig) {
                            if (col < S_DIM)
                                out[base * S_DIM + col] = v + __ldg(&bo[col]);
                            else if (col == S_DIM)
                                out[NT60 + base] = v + __ldg(&bo[S_DIM]);
                        } else {
                            if (col < S_DIM) {
                                float x = v + __ldg(&bo[col]);
                                out[NT30 + base * S_DIM + col] =
                                    sig_transform(x, __ldg(&max_lv_s[col]),
                                                     __ldg(&min_lv_s[col]));
                            } else if (col == S_DIM) {
                                float x = v + __ldg(&bo[S_DIM]);
                                out[NT61 + base] =
                                    sig_transform(x, __ldg(&max_lv_r[0]),
                                                     __ldg(&min_lv_r[0]));
                            }
                        }
                    }
                }
            }
        }
    }
}

extern "C" void kernel_launch(void* const* d_in, const int* in_sizes, int n_in,
                              void* d_out, int out_size) {
    const float* s       = (const float*)d_in[0];
    const float* a       = (const float*)d_in[1];
    const float* W1      = (const float*)d_in[2];
    const float* b1      = (const float*)d_in[3];
    const float* Wh      = (const float*)d_in[4];
    const float* bh      = (const float*)d_in[5];
    const float* Wmu     = (const float*)d_in[6];
    const float* bmu     = (const float*)d_in[7];
    const float* Wsig    = (const float*)d_in[8];
    const float* bsig    = (const float*)d_in[9];
    const float* max_lvs = (const float*)d_in[10];
    const float* min_lvs = (const float*)d_in[11];
    const float* max_lvr = (const float*)d_in[12];
    const float* min_lvr = (const float*)d_in[13];
    float* out = (float*)d_out;

    const int N = in_sizes[0] / (ENS * S_DIM);   // 32768

    cudaFuncSetAttribute(ensemble_env_prob_hmma7,
                         cudaFuncAttributeMaxDynamicSharedMemorySize, SM_TOTAL);

    prep_weights<<<dim3(NCHUNKS, ENS), 256>>>(W1, Wh, Wmu, Wsig);

    dim3 grid(N / TSAMP, ENS);                   // 256 x 7 = 1792 CTAs
    ensemble_env_prob_hmma7<<<grid, NTH, SM_TOTAL>>>(
        s, a, b1, bh, bmu, bsig,
        max_lvs, min_lvs, max_lvr, min_lvr, out, N);
}

// round 17
// speedup vs baseline: 1.2015x; 1.2015x over previous
#include <cuda_runtime.h>
#include <cuda_fp16.h>
#include <cstdint>
#include <cstddef>

#define ENS     7
#define S_DIM   30
#define A_DIM   8
#define IN_DIM  38
#define HID     200
#define OUT_DIM 31
#define NHID    3
#define TSAMP   64
#define NTH     256

// ---- B chunk image: 224 rows x 40 halfs (row stride 20 words) ----
#define BWH     40
#define BIMG_W  4480                      // words per chunk image (224*20)
#define BIMG_B  (BIMG_W * 4)              // 17920 bytes
#define NCHUNKS 30                        // 2 (L0) + 3*7 (hidden) + 7 (head)
#define NPAIRS  15

// ---- SMEM layout (bytes), per CTA = 99328 -> 2 CTAs/SM ----
#define AW      216
#define SM_A    0
#define SM_B0   (TSAMP * AW * 2)          // 27648
#define SM_TOTAL (SM_B0 + 4 * BIMG_B)     // 99328

// ---- pre-packed weight images (global scratch; L2-resident, 3.76 MB) ----
__device__ __align__(16) uint32_t g_wimg[ENS * NCHUNKS * BIMG_W];

__device__ __forceinline__ const uint32_t* chunk_src(int e, int g) {
    return g_wimg + (size_t)(e * NCHUNKS + g) * BIMG_W;
}

__device__ __forceinline__ void mma16816(float* d, const uint32_t* a, const uint32_t* b) {
    asm volatile(
        "mma.sync.aligned.m16n8k16.row.col.f32.f16.f16.f32 "
        "{%0,%1,%2,%3}, {%4,%5,%6,%7}, {%8,%9}, {%0,%1,%2,%3};"
        : "+f"(d[0]), "+f"(d[1]), "+f"(d[2]), "+f"(d[3])
        : "r"(a[0]), "r"(a[1]), "r"(a[2]), "r"(a[3]),
          "r"(b[0]), "r"(b[1]));
}
__device__ __forceinline__ void ldsm4(uint32_t* r, uint32_t addr) {
    asm volatile("ldmatrix.sync.aligned.m8n8.x4.shared.b16 {%0,%1,%2,%3}, [%4];"
        : "=r"(r[0]), "=r"(r[1]), "=r"(r[2]), "=r"(r[3]) : "r"(addr));
}
__device__ __forceinline__ void ldsm2(uint32_t* r, uint32_t addr) {
    asm volatile("ldmatrix.sync.aligned.m8n8.x2.shared.b16 {%0,%1}, [%2];"
        : "=r"(r[0]), "=r"(r[1]) : "r"(addr));
}
__device__ __forceinline__ void cp16(uint32_t smem_dst, const void* gptr) {
    asm volatile("cp.async.cg.shared.global [%0], [%1], 16;\n"
        :: "r"(smem_dst), "l"(gptr));
}
#define CP_COMMIT() asm volatile("cp.async.commit_group;\n" ::: "memory")
#define CP_WAIT0()  asm volatile("cp.async.wait_group 0;\n" ::: "memory")
#define CP_WAIT1()  asm volatile("cp.async.wait_group 1;\n" ::: "memory")

__device__ __forceinline__ uint32_t pack2h(float x, float y) {
    __half2 h = __floats2half2_rn(x, y);
    return *reinterpret_cast<uint32_t*>(&h);
}
__device__ __forceinline__ float swishf(float x) {
    return __fdividef(x, 1.0f + __expf(-x));
}
__device__ __forceinline__ float softplusf(float z) {
    return fmaxf(z, 0.0f) + log1pf(__expf(-fabsf(z)));
}
__device__ __forceinline__ float sig_transform(float x, float mx, float mn) {
    float t = (mx - softplusf(mx - 2.0f * x)) * 0.5f;
    t = (mn + softplusf(2.0f * t - mn)) * 0.5f;
    return __expf(t);
}

// ================= prep: pack all weights into chunk images (once) =================
__global__ void prep_weights(const float* __restrict__ W1, const float* __restrict__ Wh,
                             const float* __restrict__ Wmu, const float* __restrict__ Wsig) {
    const int g = blockIdx.x, e = blockIdx.y, tid = threadIdx.x;
    uint32_t* dst = g_wimg + (size_t)(e * NCHUNKS + g) * BIMG_W;
    const float* W = nullptr; const float* W2 = nullptr;
    int krows = HID, c;
    bool head = false;
    if (g < 2)       { c = g;      W = W1 + (size_t)e * IN_DIM * HID; krows = IN_DIM; }
    else if (g < 23) { int t = g - 2; int l = t / 7; c = t % 7;
                       W = Wh + ((size_t)l * ENS + e) * HID * HID; }
    else             { head = true; c = g - 23;
                       W  = Wmu  + (size_t)e * HID * OUT_DIM;
                       W2 = Wsig + (size_t)e * HID * OUT_DIM; }
    for (int w = tid; w < BIMG_W; w += 256) {
        int n = w / 20, slot = w % 20;
        float w0 = 0.f, w1 = 0.f;
        if (slot < 16) {
            int j = c * 32 + 2 * slot;
            if (!head) {
                if (n < HID) {
                    if (j < krows)     w0 = __ldg(&W[(size_t)j * HID + n]);
                    if (j + 1 < krows) w1 = __ldg(&W[(size_t)(j + 1) * HID + n]);
                }
            } else {
                if (n < OUT_DIM) {
                    if (j < HID)     w0 = __ldg(&W[(size_t)j * OUT_DIM + n]);
                    if (j + 1 < HID) w1 = __ldg(&W[(size_t)(j + 1) * OUT_DIM + n]);
                } else if (n >= 32 && n < 32 + OUT_DIM) {
                    int nn = n - 32;
                    if (j < HID)     w0 = __ldg(&W2[(size_t)j * OUT_DIM + nn]);
                    if (j + 1 < HID) w1 = __ldg(&W2[(size_t)(j + 1) * OUT_DIM + nn]);
                }
            }
        }
        dst[w] = pack2h(w0, w1);
    }
}

// ---- stage one PAIR of chunk images (2240 x 16B cp.async, 256 thr) ----
// dst = contiguous 2-slot region; src = chunk_src(e, 2p) (images contiguous)
__device__ __forceinline__ void stage_pair(uint32_t dst, const uint32_t* src, int tid) {
#pragma unroll
    for (int k = 0; k < 8; ++k) {
        int line = k * NTH + tid;
        cp16(dst + line * 16, src + line * 4);
    }
    if (tid < 192) {
        int line = 2048 + tid;
        cp16(dst + line * 16, src + line * 4);
    }
}

__global__ __launch_bounds__(NTH, 2)
void ensemble_env_prob_hmma8(
    const float* __restrict__ s, const float* __restrict__ a,
    const float* __restrict__ b1, const float* __restrict__ bh,
    const float* __restrict__ bmu, const float* __restrict__ bsig,
    const float* __restrict__ max_lv_s, const float* __restrict__ min_lv_s,
    const float* __restrict__ max_lv_r, const float* __restrict__ min_lv_r,
    float* __restrict__ out, int N)
{
    extern __shared__ char smc[];
    const uint32_t smb = (uint32_t)__cvta_generic_to_shared(smc);
    const int tid  = threadIdx.x;
    const int wid  = tid >> 5;
    const int lane = tid & 31;
    const int wm   = wid >> 2;         // 2 m-groups x 32 rows
    const int wn   = wid & 3;          // 4 n-groups x 56 cols (head: 16 cols)
    const int e    = blockIdx.y;
    const int n0   = blockIdx.x * TSAMP;

    const uint32_t bufB = smb + SM_B0;   // 4 image slots; pair p base slot = (p&1)*2

    // ldmatrix per-lane address components
    const int aRow0  = wm * 32 + (lane & 15);
    const int aColL  = (lane >> 4) * 8;
    const uint32_t aBase = smb + SM_A + aRow0 * (AW * 2);
    const int bRowL  = (lane & 7) + ((lane >> 4) << 3);
    const int bKoffL = ((lane >> 3) & 1) * 8;
    const uint32_t bLane = bRowL * (BWH * 2) + bKoffL * 2;

    // prologue: stage pairs 0 and 1 (fills all 4 slots)
    stage_pair(bufB,             chunk_src(e, 0), tid); CP_COMMIT();
    stage_pair(bufB + 2 * BIMG_B, chunk_src(e, 2), tid); CP_COMMIT();

    // ---- zero A (covers all k padding)
    for (int i = tid; i < (TSAMP * AW) / 2; i += NTH)
        ((uint32_t*)smc)[i] = 0u;
    __syncthreads();

    // ---- stage x = concat(s, a), fp16 into A
#pragma unroll
    for (int it = 0; it < 16; ++it) {
        int idx = it * NTH + tid;          // 4096 = 64 rows x 64 slots
        int m = idx >> 6, k = idx & 63;
        if (k < IN_DIM) {
            int n = n0 + m;
            float v = (k < S_DIM)
                    ? __ldg(&s[((size_t)n * ENS + e) * S_DIM + k])
                    : __ldg(&a[((size_t)n * ENS + e) * A_DIM + (k - S_DIM)]);
            *(uint16_t*)(smc + SM_A + m * (AW * 2) + k * 2) =
                __half_as_ushort(__float2half_rn(v));
        }
    }
    __syncthreads();                       // A staged before first MMA

    float acc[2][7][4];                    // [mf][nt][q]
    int g = 0;                             // global chunk counter

    // ================= layers 1..4 (swish epilogue back into A) =================
#pragma unroll 1
    for (int l = 0; l < 1 + NHID; ++l) {
        const float* bi = (l == 0) ? (b1 + (size_t)e * HID)
                                   : (bh + ((size_t)(l - 1) * ENS + e) * HID);
        const int nks = (l == 0) ? 3 : 13;
        const int nch = (nks + 1) >> 1;

#pragma unroll
        for (int mf = 0; mf < 2; ++mf)
#pragma unroll
            for (int nt = 0; nt < 7; ++nt)
#pragma unroll
                for (int q = 0; q < 4; ++q) acc[mf][nt][q] = 0.f;

#pragma unroll 1
        for (int c = 0; c < nch; ++c) {
            if ((g & 1) == 0) {            // pair boundary
                const int p = g >> 1;
                if (p == 0) { CP_WAIT1(); } else { CP_WAIT0(); }
                __syncthreads();           // pair p landed; pair p-1 slots free
                if (p >= 1 && p + 1 < NPAIRS) {
                    stage_pair(bufB + (((p + 1) & 1) * 2) * BIMG_B,
                               chunk_src(e, 2 * (p + 1)), tid);
                    CP_COMMIT();
                }
            }
            const uint32_t slot = (((g >> 1) & 1) << 1) | (g & 1);
            const uint32_t bB = bufB + slot * BIMG_B + bLane + (wn * 56) * (BWH * 2);
            const int nk = (nks - 2 * c > 2) ? 2 : (nks - 2 * c);
#pragma unroll
            for (int ks = 0; ks < 2; ++ks) {
                if (ks >= nk) break;
                const int kA = c * 32 + ks * 16 + aColL;
                uint32_t ah[2][4];
                ldsm4(ah[0], aBase + kA * 2);
                ldsm4(ah[1], aBase + 16 * (AW * 2) + kA * 2);
                const uint32_t bk = bB + (ks * 16) * 2;
#pragma unroll
                for (int ntp = 0; ntp < 3; ++ntp) {
                    uint32_t b4[4];
                    ldsm4(b4, bk + (ntp * 16) * (BWH * 2));
#pragma unroll
                    for (int mf = 0; mf < 2; ++mf) {
                        mma16816(acc[mf][2 * ntp],     ah[mf], b4);
                        mma16816(acc[mf][2 * ntp + 1], ah[mf], b4 + 2);
                    }
                }
                {
                    uint32_t b2[2];
                    ldsm2(b2, bk + 48 * (BWH * 2));
#pragma unroll
                    for (int mf = 0; mf < 2; ++mf)
                        mma16816(acc[mf][6], ah[mf], b2);
                }
            }
            ++g;
        }
        __syncthreads();                           // all A reads done before overwrite

        // ---- epilogue: +bias, swish, fp16, back into A (cols < 200)
        const int rr = wm * 32 + (lane >> 2);
#pragma unroll
        for (int nt = 0; nt < 7; ++nt) {
            int cc = wn * 56 + nt * 8 + (lane & 3) * 2;
            if (cc < HID) {
                float b0  = __ldg(&bi[cc]);
                float b1v = __ldg(&bi[cc + 1]);
#pragma unroll
                for (int mf = 0; mf < 2; ++mf) {
#pragma unroll
                    for (int rp = 0; rp < 2; ++rp) {
                        int row = rr + mf * 16 + rp * 8;
                        float h0 = swishf(acc[mf][nt][rp * 2]     + b0);
                        float h1 = swishf(acc[mf][nt][rp * 2 + 1] + b1v);
                        *(uint32_t*)(smc + SM_A + row * (AW * 2) + cc * 2) =
                            pack2h(h0, h1);
                    }
                }
            }
        }
        __syncthreads();                           // A writes visible before next MMA
    }

    // ================= head: packed [mu | sig], N = 64, warp covers 16 cols ========
#pragma unroll
    for (int mf = 0; mf < 2; ++mf)
#pragma unroll
        for (int nt = 0; nt < 2; ++nt)
#pragma unroll
            for (int q = 0; q < 4; ++q) acc[mf][nt][q] = 0.f;

#pragma unroll 1
    for (int c = 0; c < 7; ++c) {
        if ((g & 1) == 0) {                // pair boundary
            const int p = g >> 1;
            CP_WAIT0();
            __syncthreads();
            if (p >= 1 && p + 1 < NPAIRS) {
                stage_pair(bufB + (((p + 1) & 1) * 2) * BIMG_B,
                           chunk_src(e, 2 * (p + 1)), tid);
                CP_COMMIT();
            }
        }
        const uint32_t slot = (((g >> 1) & 1) << 1) | (g & 1);
        const uint32_t bB = bufB + slot * BIMG_B + bLane + (wn * 16) * (BWH * 2);
        const int nk = (13 - 2 * c > 2) ? 2 : (13 - 2 * c);
#pragma unroll
        for (int ks = 0; ks < 2; ++ks) {
            if (ks >= nk) break;
            const int kA = c * 32 + ks * 16 + aColL;
            uint32_t ah[2][4];
            ldsm4(ah[0], aBase + kA * 2);
            ldsm4(ah[1], aBase + 16 * (AW * 2) + kA * 2);
            uint32_t b4[4];
            ldsm4(b4, bB + (ks * 16) * 2);
#pragma unroll
            for (int mf = 0; mf < 2; ++mf) {
                mma16816(acc[mf][0], ah[mf], b4);
                mma16816(acc[mf][1], ah[mf], b4 + 2);
            }
        }
        ++g;
    }

    // ================= head epilogue: direct global stores =================
    {
        const size_t NT_  = (size_t)N * ENS;
        const size_t NT30 = NT_ * 30, NT60 = NT_ * 60, NT61 = NT_ * 61;
        const bool  is_sig = (wn >= 2);
        const float* bo = (is_sig ? bsig : bmu) + (size_t)e * OUT_DIM;
        const int rr = wm * 32 + (lane >> 2);
#pragma unroll
        for (int mf = 0; mf < 2; ++mf) {
#pragma unroll
            for (int rp = 0; rp < 2; ++rp) {
                int row = rr + mf * 16 + rp * 8;
                size_t base = ((size_t)(n0 + row) * ENS + e);
#pragma unroll
                for (int nt = 0; nt < 2; ++nt) {
#pragma unroll
                    for (int i = 0; i < 2; ++i) {
                        int colg = wn * 16 + nt * 8 + (lane & 3) * 2 + i;  // 0..63
                        int col  = is_sig ? (colg - 32) : colg;            // 0..31
                        float v = acc[mf][nt][rp * 2 + i];
                        if (!is_sig) {
                            if (col < S_DIM)
                                out[base * S_DIM + col] = v + __ldg(&bo[col]);
                            else if (col == S_DIM)
                                out[NT60 + base] = v + __ldg(&bo[S_DIM]);
                        } else {
                            if (col < S_DIM) {
                                float x = v + __ldg(&bo[col]);
                                out[NT30 + base * S_DIM + col] =
                                    sig_transform(x, __ldg(&max_lv_s[col]),
                                                     __ldg(&min_lv_s[col]));
                            } else if (col == S_DIM) {
                                float x = v + __ldg(&bo[S_DIM]);
                                out[NT61 + base] =
                                    sig_transform(x, __ldg(&max_lv_r[0]),
                                                     __ldg(&min_lv_r[0]));
                            }
                        }
                    }
                }
            }
        }
    }
}

extern "C" void kernel_launch(void* const* d_in, const int* in_sizes, int n_in,
                              void* d_out, int out_size) {
    const float* s       = (const float*)d_in[0];
    const float* a       = (const float*)d_in[1];
    const float* W1      = (const float*)d_in[2];
    const float* b1      = (const float*)d_in[3];
    const float* Wh      = (const float*)d_in[4];
    const float* bh      = (const float*)d_in[5];
    const float* Wmu     = (const float*)d_in[6];
    const float* bmu     = (const float*)d_in[7];
    const float* Wsig    = (const float*)d_in[8];
    const float* bsig    = (const float*)d_in[9];
    const float* max_lvs = (const float*)d_in[10];
    const float* min_lvs = (const float*)d_in[11];
    const float* max_lvr = (const float*)d_in[12];
    const float* min_lvr = (const float*)d_in[13];
    float* out = (float*)d_out;

    const int N = in_sizes[0] / (ENS * S_DIM);   // 32768

    cudaFuncSetAttribute(ensemble_env_prob_hmma8,
                         cudaFuncAttributeMaxDynamicSharedMemorySize, SM_TOTAL);

    prep_weights<<<dim3(NCHUNKS, ENS), 256>>>(W1, Wh, Wmu, Wsig);

    dim3 grid(N / TSAMP, ENS);                   // 512 x 7 = 3584 CTAs
    ensemble_env_prob_hmma8<<<grid, NTH, SM_TOTAL>>>(
        s, a, b1, bh, bmu, bsig,
        max_lvs, min_lvs, max_lvr, min_lvr, out, N);
}